// round 15
// baseline (speedup 1.0000x reference)
#include <cuda_runtime.h>
#include <cuda_fp16.h>
#include <math.h>

#define T_STEPS 256
#define B_SZ    64
#define H_SZ    1024
#define NG      4096   // 4*H
#define WPAD    1032   // padded k-stride for smem-resident weights (bank-safe)
#define CH      128    // k columns per staged chunk in recurrence
#define NCH     8      // chunks per step

// ---------------- device-global scratch (allocation-free contract) ---------
__device__ __half g_Wxpk[(size_t)2 * NG * 1024];            // [s][n'=j*4+g][k] hi/lo
__device__ __half g_Whpk[(size_t)128 * 32 * 1024];          // [blk][n32][k] hi only
__device__ float  g_bpk[NG];
__device__ __half g_axh[(size_t)T_STEPS * B_SZ * 1024];     // quantized x
__device__ float  g_Xpre[(size_t)T_STEPS * B_SZ * NG];
__device__ __half g_ah[2][B_SZ * H_SZ];                     // h (fp16), dbl-buffered
__device__ unsigned g_cnt[NCH];                             // producer-group flags

#define U32(x) (*reinterpret_cast<const unsigned*>(&(x)))

__device__ __forceinline__ void mma16816(float* c, const unsigned* a, const unsigned* b) {
    asm volatile(
        "mma.sync.aligned.m16n8k16.row.col.f32.f16.f16.f32 "
        "{%0,%1,%2,%3}, {%4,%5,%6,%7}, {%8,%9}, {%0,%1,%2,%3};\n"
        : "+f"(c[0]), "+f"(c[1]), "+f"(c[2]), "+f"(c[3])
        : "r"(a[0]), "r"(a[1]), "r"(a[2]), "r"(a[3]), "r"(b[0]), "r"(b[1]));
}

__device__ __forceinline__ void cp16(void* smem_dst, const void* gsrc) {
    unsigned s = (unsigned)__cvta_generic_to_shared(smem_dst);
    asm volatile("cp.async.cg.shared.global [%0], [%1], 16;\n" :: "r"(s), "l"(gsrc));
}

__device__ __forceinline__ unsigned ldacq(const unsigned* p) {
    unsigned v;
    asm volatile("ld.acquire.gpu.global.u32 %0, [%1];" : "=r"(v) : "l"(p) : "memory");
    return v;
}

__device__ __forceinline__ void spin_ge(const unsigned* p, unsigned tgt) {
    while (ldacq(p) < tgt) { }
}

// ---------------------------------------------------------------------------
// Pack weights: Wx split hi/lo (compensated), Wh hi-only; gate-interleaved,
// n-major; per-block gather for the recurrence.
// ---------------------------------------------------------------------------
__global__ void pack_weights(const float* __restrict__ Wff, const float* __restrict__ bff,
                             const float* __restrict__ Wii, const float* __restrict__ bii,
                             const float* __restrict__ Wgg, const float* __restrict__ bgg,
                             const float* __restrict__ Woo, const float* __restrict__ boo) {
    int idx = blockIdx.x * blockDim.x + threadIdx.x;
    if (idx >= 1024 * 1024) return;
    int j = idx >> 10, k = idx & 1023;
    const float* Wm[4] = {Wff, Wii, Wgg, Woo};
    const float* bm[4] = {bff, bii, bgg, boo};
#pragma unroll
    for (int g = 0; g < 4; g++) {
        float vx = Wm[g][(size_t)j * 2048 + k];
        float vh = Wm[g][(size_t)j * 2048 + 1024 + k];
        __half xh = __float2half_rn(vx);
        __half xl = __float2half_rn(vx - __half2float(xh));
        __half hh = __float2half_rn(vh);
        int np = j * 4 + g;
        g_Wxpk[(size_t)np * 1024 + k]        = xh;
        g_Wxpk[(size_t)(NG + np) * 1024 + k] = xl;
        int b = j >> 3, jl = j & 7, n32 = jl * 4 + g;
        g_Whpk[((size_t)b * 32 + n32) * 1024 + k] = hh;
        if (k == 0) g_bpk[np] = bm[g][j];
    }
}

__global__ void convert_x(const float* __restrict__ x) {
    int idx = blockIdx.x * blockDim.x + threadIdx.x;
    if (idx >= T_STEPS * B_SZ * 1024) return;
    g_axh[idx] = __float2half_rn(x[idx]);
}

__global__ void zero_state() {
    int i = blockIdx.x * blockDim.x + threadIdx.x;
    if (i < B_SZ * H_SZ) {
        g_ah[0][i] = __float2half_rn(0.f);
    }
    if (blockIdx.x == 0 && threadIdx.x < NCH) g_cnt[threadIdx.x] = 0u;
}

// ---------------------------------------------------------------------------
// Precompute: Xpre = x_q @ (Wx_h + Wx_l), 2-pass compensated weights.
// 128x128 tile, BK=32, 2-stage cp.async pipeline.
// ---------------------------------------------------------------------------
#define GX_SMEM (6 * 128 * 40 * 2)   // 3 arrays x 2 stages x 128x40 halves

__device__ __forceinline__ void gx_issue(char* sm, int st, int kc, int tid, int mb, int nb) {
    __half(*Axh)[128][40] = reinterpret_cast<__half(*)[128][40]>(sm);
    __half(*Whs)[128][40] = reinterpret_cast<__half(*)[128][40]>(sm + 20480);
    __half(*Wls)[128][40] = reinterpret_cast<__half(*)[128][40]>(sm + 40960);
    const int k0 = kc * 32;
#pragma unroll
    for (int i = 0; i < 2; i++) {
        int e = tid + i * 256;
        int row = e >> 2, cg = e & 3;
        cp16(&Axh[st][row][cg * 8], &g_axh[(size_t)(mb * 128 + row) * 1024 + k0 + cg * 8]);
        cp16(&Whs[st][row][cg * 8], &g_Wxpk[(size_t)(nb * 128 + row) * 1024 + k0 + cg * 8]);
        cp16(&Wls[st][row][cg * 8], &g_Wxpk[(size_t)(NG + nb * 128 + row) * 1024 + k0 + cg * 8]);
    }
    asm volatile("cp.async.commit_group;\n" ::);
}

__global__ __launch_bounds__(256, 2) void gemm_xpre() {
    extern __shared__ char sm[];
    __half(*Axh)[128][40] = reinterpret_cast<__half(*)[128][40]>(sm);
    __half(*Whs)[128][40] = reinterpret_cast<__half(*)[128][40]>(sm + 20480);
    __half(*Wls)[128][40] = reinterpret_cast<__half(*)[128][40]>(sm + 40960);

    const int tid = threadIdx.x;
    const int lane = tid & 31, w = tid >> 5;
    const int grp = lane >> 2, t4 = lane & 3;
    const int wm = w >> 2, wn = w & 3;
    const int nb = blockIdx.x, mb = blockIdx.y;

    float acc[4][4][4];
#pragma unroll
    for (int m = 0; m < 4; m++)
#pragma unroll
        for (int n = 0; n < 4; n++)
#pragma unroll
            for (int i = 0; i < 4; i++) acc[m][n][i] = 0.f;

    gx_issue(sm, 0, 0, tid, mb, nb);

    for (int kc = 0; kc < 32; ++kc) {
        const int cur = kc & 1;
        if (kc + 1 < 32) gx_issue(sm, cur ^ 1, kc + 1, tid, mb, nb);
        if (kc + 1 < 32) asm volatile("cp.async.wait_group 1;\n" ::);
        else             asm volatile("cp.async.wait_group 0;\n" ::);
        __syncthreads();

#pragma unroll
        for (int kk = 0; kk < 32; kk += 16) {
            unsigned af[4][4], bf2[4][2];
            const int c = kk + 2 * t4;
#pragma unroll
            for (int m = 0; m < 4; m++) {
                int r = wm * 64 + m * 16 + grp;
                af[m][0] = U32(Axh[cur][r][c]);     af[m][1] = U32(Axh[cur][r + 8][c]);
                af[m][2] = U32(Axh[cur][r][c + 8]); af[m][3] = U32(Axh[cur][r + 8][c + 8]);
            }
#pragma unroll
            for (int n = 0; n < 4; n++) {
                int rn = wn * 32 + n * 8 + grp;
                bf2[n][0] = U32(Whs[cur][rn][c]); bf2[n][1] = U32(Whs[cur][rn][c + 8]);
            }
#pragma unroll
            for (int m = 0; m < 4; m++)
#pragma unroll
                for (int n = 0; n < 4; n++) mma16816(acc[m][n], af[m], bf2[n]);
#pragma unroll
            for (int n = 0; n < 4; n++) {
                int rn = wn * 32 + n * 8 + grp;
                bf2[n][0] = U32(Wls[cur][rn][c]); bf2[n][1] = U32(Wls[cur][rn][c + 8]);
            }
#pragma unroll
            for (int m = 0; m < 4; m++)
#pragma unroll
                for (int n = 0; n < 4; n++) mma16816(acc[m][n], af[m], bf2[n]);
        }
        __syncthreads();
    }

#pragma unroll
    for (int m = 0; m < 4; m++) {
        int r = mb * 128 + wm * 64 + m * 16 + grp;
#pragma unroll
        for (int n = 0; n < 4; n++) {
            int cn = nb * 128 + wn * 32 + n * 8 + 2 * t4;
            float b0 = __ldg(&g_bpk[cn]), b1 = __ldg(&g_bpk[cn + 1]);
            float2 v0 = make_float2(acc[m][n][0] + b0, acc[m][n][1] + b1);
            float2 v1 = make_float2(acc[m][n][2] + b0, acc[m][n][3] + b1);
            *reinterpret_cast<float2*>(&g_Xpre[(size_t)r * NG + cn]) = v0;
            *reinterpret_cast<float2*>(&g_Xpre[(size_t)(r + 8) * NG + cn]) = v1;
        }
    }
}

// ---------------------------------------------------------------------------
// Persistent recurrence, fine-grained sync. 128 blocks x 256 threads.
// Single MMA pass: h_q * Wh_h. Per-chunk producer-group flags.
// ---------------------------------------------------------------------------
#define LS_W_OFF   0
#define LS_AH_OFF  (32 * WPAD * 2)              // 66048
#define LS_Z_OFF   (LS_AH_OFF + 2 * 64 * 136 * 2)
#define LS_SMEM    (LS_Z_OFF + 64 * 36 * 4)     // ~110 KB

__global__ __launch_bounds__(256, 1) void lstm_persist(float* __restrict__ out,
                                                       float* __restrict__ out_tail) {
    extern __shared__ char sm[];
    __half(*Wsp)[WPAD]      = reinterpret_cast<__half(*)[WPAD]>(sm + LS_W_OFF);   // [32][WPAD]
    __half(*Ah)[64][136]    = reinterpret_cast<__half(*)[64][136]>(sm + LS_AH_OFF);
    float(*zsm)[36]         = reinterpret_cast<float(*)[36]>(sm + LS_Z_OFF);

    const int tid = threadIdx.x;
    const int lane = tid & 31, w = tid >> 5;
    const int grp = lane >> 2, t4 = lane & 3;
    const int mf = w & 3, np = w >> 2;
    const int hb8 = blockIdx.x * 8;
    const int arow = tid >> 2, acseg = (tid & 3) * 32;   // staging map
    const unsigned mygrp = (unsigned)(blockIdx.x >> 4);

    // ---- load this block's Wh slice (32 n-rows x 1024 k) once ----
    const size_t wsrc = (size_t)blockIdx.x * 32768;
    for (int i = tid; i < 4096; i += 256) {
        int sn = i >> 7, kc8 = i & 127;
        *reinterpret_cast<float4*>(&Wsp[sn][kc8 * 8]) =
            *reinterpret_cast<const float4*>(&g_Whpk[wsrc + (size_t)sn * 1024 + kc8 * 8]);
    }
    __syncthreads();

    float c_reg[2] = {0.f, 0.f};

#pragma unroll 1
    for (int t = 0; t < T_STEPS; t++) {
        const __half* __restrict__ ah_in = g_ah[t & 1];
        __half* __restrict__ ah_out = g_ah[(t + 1) & 1];
        const float* __restrict__ xpre_t = g_Xpre + (size_t)t * (B_SZ * NG);
        float* __restrict__ out_t = out + (size_t)t * (B_SZ * H_SZ);
        const unsigned tgt = 16u * (unsigned)t;

        // prefetch this step's xpre gate-vectors
        float4 xp[2];
#pragma unroll
        for (int i = 0; i < 2; i++) {
            int p = tid + i * 256;
            int b = p >> 3, jl = p & 7;
            xp[i] = *reinterpret_cast<const float4*>(&xpre_t[(size_t)b * NG + (hb8 + jl) * 4]);
        }

        float acc[2][4] = {{0.f, 0.f, 0.f, 0.f}, {0.f, 0.f, 0.f, 0.f}};

        // chunk 0: wait + load into buf 0
        if (t) spin_ge(&g_cnt[0], tgt);
        {
            const __half* src = &ah_in[arow * 1024 + acseg];
            float4 s0 = *reinterpret_cast<const float4*>(src);
            float4 s1 = *reinterpret_cast<const float4*>(src + 8);
            float4 s2 = *reinterpret_cast<const float4*>(src + 16);
            float4 s3 = *reinterpret_cast<const float4*>(src + 24);
            __half* dst = &Ah[0][arow][acseg];
            *reinterpret_cast<float4*>(dst)      = s0;
            *reinterpret_cast<float4*>(dst + 8)  = s1;
            *reinterpret_cast<float4*>(dst + 16) = s2;
            *reinterpret_cast<float4*>(dst + 24) = s3;
        }
        __syncthreads();

#pragma unroll 1
        for (int c = 0; c < NCH; c++) {
            const int cur = c & 1;
            float4 r0v, r1v, r2v, r3v;
            if (c < NCH - 1) {
                if (t) spin_ge(&g_cnt[c + 1], tgt);
                const __half* src = &ah_in[arow * 1024 + (c + 1) * CH + acseg];
                r0v = *reinterpret_cast<const float4*>(src);
                r1v = *reinterpret_cast<const float4*>(src + 8);
                r2v = *reinterpret_cast<const float4*>(src + 16);
                r3v = *reinterpret_cast<const float4*>(src + 24);
            }
#pragma unroll
            for (int kk = 0; kk < CH; kk += 16) {
                const int r0 = mf * 16 + grp;
                const int cs = kk + 2 * t4;
                const int c0 = c * CH + cs;
                unsigned a[4], bh[2][2];
                a[0] = U32(Ah[cur][r0][cs]);     a[1] = U32(Ah[cur][r0 + 8][cs]);
                a[2] = U32(Ah[cur][r0][cs + 8]); a[3] = U32(Ah[cur][r0 + 8][cs + 8]);
#pragma unroll
                for (int q = 0; q < 2; q++) {
                    int n0 = (np * 2 + q) * 8 + grp;
                    bh[q][0] = U32(Wsp[n0][c0]); bh[q][1] = U32(Wsp[n0][c0 + 8]);
                }
                mma16816(acc[0], a, bh[0]); mma16816(acc[1], a, bh[1]);
            }
            if (c < NCH - 1) {
                __half* dst = &Ah[cur ^ 1][arow][acseg];
                *reinterpret_cast<float4*>(dst)      = r0v;
                *reinterpret_cast<float4*>(dst + 8)  = r1v;
                *reinterpret_cast<float4*>(dst + 16) = r2v;
                *reinterpret_cast<float4*>(dst + 24) = r3v;
            }
            __syncthreads();
        }

        // z exchange
#pragma unroll
        for (int q = 0; q < 2; q++) {
            int n0 = (np * 2 + q) * 8 + 2 * t4;
            int r0 = mf * 16 + grp;
            zsm[r0][n0]         = acc[q][0];
            zsm[r0][n0 + 1]     = acc[q][1];
            zsm[r0 + 8][n0]     = acc[q][2];
            zsm[r0 + 8][n0 + 1] = acc[q][3];
        }
        __syncthreads();

        // gate math + state update; publish h first, then arrive, then out
        float hn_r[2], cn_r[2];
        int idx_r[2];
#pragma unroll
        for (int i = 0; i < 2; i++) {
            int p = tid + i * 256;
            int b = p >> 3, jl = p & 7;
            int hb = hb8 + jl;
            float zf = zsm[b][jl * 4 + 0] + xp[i].x;
            float zi = zsm[b][jl * 4 + 1] + xp[i].y;
            float zg = zsm[b][jl * 4 + 2] + xp[i].z;
            float zo = zsm[b][jl * 4 + 3] + xp[i].w;
            float f  = 1.f / (1.f + expf(-zf));
            float ig = 1.f / (1.f + expf(-zi));
            float gg = tanhf(zg);
            float oo = 1.f / (1.f + expf(-zo));
            int idx = (b << 10) + hb;
            float cn = f * c_reg[i] + ig * gg;
            c_reg[i] = cn;
            float hn = oo * tanhf(cn);
            ah_out[idx] = __float2half_rn(hn);
            hn_r[i] = hn; cn_r[i] = cn; idx_r[i] = idx;
        }
        __threadfence();
        __syncthreads();
        if (tid == 0) atomicAdd(&g_cnt[mygrp], 1u);

#pragma unroll
        for (int i = 0; i < 2; i++) out_t[idx_r[i]] = hn_r[i];
        if (t == T_STEPS - 1 && out_tail) {
#pragma unroll
            for (int i = 0; i < 2; i++) {
                out_tail[idx_r[i]] = hn_r[i];
                out_tail[B_SZ * H_SZ + idx_r[i]] = cn_r[i];
            }
        }
    }
}

extern "C" void kernel_launch(void* const* d_in, const int* in_sizes, int n_in,
                              void* d_out, int out_size) {
    const float* inputs = (const float*)d_in[0];
    const float* Wf = (const float*)d_in[1];
    const float* bf = (const float*)d_in[2];
    const float* Wi = (const float*)d_in[3];
    const float* bi = (const float*)d_in[4];
    const float* Wg = (const float*)d_in[5];
    const float* bg = (const float*)d_in[6];
    const float* Wo = (const float*)d_in[7];
    const float* bo = (const float*)d_in[8];
    float* out = (float*)d_out;

    cudaFuncSetAttribute(gemm_xpre, cudaFuncAttributeMaxDynamicSharedMemorySize, GX_SMEM);
    cudaFuncSetAttribute(lstm_persist, cudaFuncAttributeMaxDynamicSharedMemorySize, LS_SMEM);

    pack_weights<<<(1024 * 1024 + 255) / 256, 256>>>(Wf, bf, Wi, bi, Wg, bg, Wo, bo);
    convert_x<<<(T_STEPS * B_SZ * 1024 + 255) / 256, 256>>>(inputs);
    zero_state<<<(B_SZ * H_SZ + 255) / 256, 256>>>();

    dim3 g1(NG / 128, (T_STEPS * B_SZ) / 128);
    gemm_xpre<<<g1, 256, GX_SMEM>>>();

    const int tail_needed = T_STEPS * B_SZ * H_SZ + 2 * B_SZ * H_SZ;
    float* out_tail = (out_size >= tail_needed) ? out + (size_t)T_STEPS * B_SZ * H_SZ : nullptr;
    lstm_persist<<<128, 256, LS_SMEM>>>(out, out_tail);
}

// round 16
// speedup vs baseline: 1.0230x; 1.0230x over previous
#include <cuda_runtime.h>
#include <cuda_fp16.h>
#include <math.h>

#define T_STEPS 256
#define B_SZ    64
#define H_SZ    1024
#define NG      4096   // 4*H
#define WPAD    1032   // padded k-stride for smem-resident weights (bank-safe)
#define CH      128    // k columns per staged chunk in recurrence
#define NCH     8      // chunks per step

// ---------------- device-global scratch (allocation-free contract) ---------
__device__ __half g_Wxpk[(size_t)2 * NG * 1024];            // [s][n'=j*4+g][k] hi/lo
__device__ __half g_Whpk[(size_t)128 * 32 * 1024];          // [blk][n32][k] hi only
__device__ float  g_bpk[NG];
__device__ __half g_axh[(size_t)T_STEPS * B_SZ * 1024];     // quantized x
__device__ float  g_Xpre[(size_t)T_STEPS * B_SZ * NG];
__device__ __half g_ah[2][B_SZ * H_SZ];                     // h (fp16), dbl-buffered
__device__ unsigned g_cnt[NCH];                             // producer-group flags

#define U32(x) (*reinterpret_cast<const unsigned*>(&(x)))

__device__ __forceinline__ void mma16816(float* c, const unsigned* a, const unsigned* b) {
    asm volatile(
        "mma.sync.aligned.m16n8k16.row.col.f32.f16.f16.f32 "
        "{%0,%1,%2,%3}, {%4,%5,%6,%7}, {%8,%9}, {%0,%1,%2,%3};\n"
        : "+f"(c[0]), "+f"(c[1]), "+f"(c[2]), "+f"(c[3])
        : "r"(a[0]), "r"(a[1]), "r"(a[2]), "r"(a[3]), "r"(b[0]), "r"(b[1]));
}

__device__ __forceinline__ void cp16(void* smem_dst, const void* gsrc) {
    unsigned s = (unsigned)__cvta_generic_to_shared(smem_dst);
    asm volatile("cp.async.cg.shared.global [%0], [%1], 16;\n" :: "r"(s), "l"(gsrc));
}

__device__ __forceinline__ unsigned ldacq(const unsigned* p) {
    unsigned v;
    asm volatile("ld.acquire.gpu.global.u32 %0, [%1];" : "=r"(v) : "l"(p) : "memory");
    return v;
}

__device__ __forceinline__ void spin_ge(const unsigned* p, unsigned tgt) {
    while (ldacq(p) < tgt) { }
}

// ---------------------------------------------------------------------------
// Pack weights: Wx split hi/lo (compensated), Wh hi-only; gate-interleaved,
// n-major; per-block gather for the recurrence.
// ---------------------------------------------------------------------------
__global__ void pack_weights(const float* __restrict__ Wff, const float* __restrict__ bff,
                             const float* __restrict__ Wii, const float* __restrict__ bii,
                             const float* __restrict__ Wgg, const float* __restrict__ bgg,
                             const float* __restrict__ Woo, const float* __restrict__ boo) {
    int idx = blockIdx.x * blockDim.x + threadIdx.x;
    if (idx >= 1024 * 1024) return;
    int j = idx >> 10, k = idx & 1023;
    const float* Wm[4] = {Wff, Wii, Wgg, Woo};
    const float* bm[4] = {bff, bii, bgg, boo};
#pragma unroll
    for (int g = 0; g < 4; g++) {
        float vx = Wm[g][(size_t)j * 2048 + k];
        float vh = Wm[g][(size_t)j * 2048 + 1024 + k];
        __half xh = __float2half_rn(vx);
        __half xl = __float2half_rn(vx - __half2float(xh));
        __half hh = __float2half_rn(vh);
        int np = j * 4 + g;
        g_Wxpk[(size_t)np * 1024 + k]        = xh;
        g_Wxpk[(size_t)(NG + np) * 1024 + k] = xl;
        int b = j >> 3, jl = j & 7, n32 = jl * 4 + g;
        g_Whpk[((size_t)b * 32 + n32) * 1024 + k] = hh;
        if (k == 0) g_bpk[np] = bm[g][j];
    }
}

__global__ void convert_x(const float* __restrict__ x) {
    int idx = blockIdx.x * blockDim.x + threadIdx.x;
    if (idx >= T_STEPS * B_SZ * 1024) return;
    g_axh[idx] = __float2half_rn(x[idx]);
}

__global__ void zero_state() {
    int i = blockIdx.x * blockDim.x + threadIdx.x;
    if (i < B_SZ * H_SZ) {
        g_ah[0][i] = __float2half_rn(0.f);
    }
    if (blockIdx.x == 0 && threadIdx.x < NCH) g_cnt[threadIdx.x] = 0u;
}

// ---------------------------------------------------------------------------
// Precompute: Xpre = x_q @ (Wx_h + Wx_l), 2-pass compensated weights.
// 128x128 tile, BK=32, 2-stage cp.async pipeline.
// ---------------------------------------------------------------------------
#define GX_SMEM (6 * 128 * 40 * 2)   // 3 arrays x 2 stages x 128x40 halves

__device__ __forceinline__ void gx_issue(char* sm, int st, int kc, int tid, int mb, int nb) {
    __half(*Axh)[128][40] = reinterpret_cast<__half(*)[128][40]>(sm);
    __half(*Whs)[128][40] = reinterpret_cast<__half(*)[128][40]>(sm + 20480);
    __half(*Wls)[128][40] = reinterpret_cast<__half(*)[128][40]>(sm + 40960);
    const int k0 = kc * 32;
#pragma unroll
    for (int i = 0; i < 2; i++) {
        int e = tid + i * 256;
        int row = e >> 2, cg = e & 3;
        cp16(&Axh[st][row][cg * 8], &g_axh[(size_t)(mb * 128 + row) * 1024 + k0 + cg * 8]);
        cp16(&Whs[st][row][cg * 8], &g_Wxpk[(size_t)(nb * 128 + row) * 1024 + k0 + cg * 8]);
        cp16(&Wls[st][row][cg * 8], &g_Wxpk[(size_t)(NG + nb * 128 + row) * 1024 + k0 + cg * 8]);
    }
    asm volatile("cp.async.commit_group;\n" ::);
}

__global__ __launch_bounds__(256, 2) void gemm_xpre() {
    extern __shared__ char sm[];
    __half(*Axh)[128][40] = reinterpret_cast<__half(*)[128][40]>(sm);
    __half(*Whs)[128][40] = reinterpret_cast<__half(*)[128][40]>(sm + 20480);
    __half(*Wls)[128][40] = reinterpret_cast<__half(*)[128][40]>(sm + 40960);

    const int tid = threadIdx.x;
    const int lane = tid & 31, w = tid >> 5;
    const int grp = lane >> 2, t4 = lane & 3;
    const int wm = w >> 2, wn = w & 3;
    const int nb = blockIdx.x, mb = blockIdx.y;

    float acc[4][4][4];
#pragma unroll
    for (int m = 0; m < 4; m++)
#pragma unroll
        for (int n = 0; n < 4; n++)
#pragma unroll
            for (int i = 0; i < 4; i++) acc[m][n][i] = 0.f;

    gx_issue(sm, 0, 0, tid, mb, nb);

    for (int kc = 0; kc < 32; ++kc) {
        const int cur = kc & 1;
        if (kc + 1 < 32) gx_issue(sm, cur ^ 1, kc + 1, tid, mb, nb);
        if (kc + 1 < 32) asm volatile("cp.async.wait_group 1;\n" ::);
        else             asm volatile("cp.async.wait_group 0;\n" ::);
        __syncthreads();

#pragma unroll
        for (int kk = 0; kk < 32; kk += 16) {
            unsigned af[4][4], bf2[4][2];
            const int c = kk + 2 * t4;
#pragma unroll
            for (int m = 0; m < 4; m++) {
                int r = wm * 64 + m * 16 + grp;
                af[m][0] = U32(Axh[cur][r][c]);     af[m][1] = U32(Axh[cur][r + 8][c]);
                af[m][2] = U32(Axh[cur][r][c + 8]); af[m][3] = U32(Axh[cur][r + 8][c + 8]);
            }
#pragma unroll
            for (int n = 0; n < 4; n++) {
                int rn = wn * 32 + n * 8 + grp;
                bf2[n][0] = U32(Whs[cur][rn][c]); bf2[n][1] = U32(Whs[cur][rn][c + 8]);
            }
#pragma unroll
            for (int m = 0; m < 4; m++)
#pragma unroll
                for (int n = 0; n < 4; n++) mma16816(acc[m][n], af[m], bf2[n]);
#pragma unroll
            for (int n = 0; n < 4; n++) {
                int rn = wn * 32 + n * 8 + grp;
                bf2[n][0] = U32(Wls[cur][rn][c]); bf2[n][1] = U32(Wls[cur][rn][c + 8]);
            }
#pragma unroll
            for (int m = 0; m < 4; m++)
#pragma unroll
                for (int n = 0; n < 4; n++) mma16816(acc[m][n], af[m], bf2[n]);
        }
        __syncthreads();
    }

#pragma unroll
    for (int m = 0; m < 4; m++) {
        int r = mb * 128 + wm * 64 + m * 16 + grp;
#pragma unroll
        for (int n = 0; n < 4; n++) {
            int cn = nb * 128 + wn * 32 + n * 8 + 2 * t4;
            float b0 = __ldg(&g_bpk[cn]), b1 = __ldg(&g_bpk[cn + 1]);
            float2 v0 = make_float2(acc[m][n][0] + b0, acc[m][n][1] + b1);
            float2 v1 = make_float2(acc[m][n][2] + b0, acc[m][n][3] + b1);
            *reinterpret_cast<float2*>(&g_Xpre[(size_t)r * NG + cn]) = v0;
            *reinterpret_cast<float2*>(&g_Xpre[(size_t)(r + 8) * NG + cn]) = v1;
        }
    }
}

// ---------------------------------------------------------------------------
// Persistent recurrence, fine-grained sync. 128 blocks x 256 threads.
// Single MMA pass: h_q * Wh_h. Per-chunk producer-group flags.
// ---------------------------------------------------------------------------
#define LS_W_OFF   0
#define LS_AH_OFF  (32 * WPAD * 2)              // 66048
#define LS_Z_OFF   (LS_AH_OFF + 2 * 64 * 136 * 2)
#define LS_SMEM    (LS_Z_OFF + 64 * 36 * 4)     // ~110 KB

__global__ __launch_bounds__(256, 1) void lstm_persist(float* __restrict__ out,
                                                       float* __restrict__ out_tail) {
    extern __shared__ char sm[];
    __half(*Wsp)[WPAD]      = reinterpret_cast<__half(*)[WPAD]>(sm + LS_W_OFF);   // [32][WPAD]
    __half(*Ah)[64][136]    = reinterpret_cast<__half(*)[64][136]>(sm + LS_AH_OFF);
    float(*zsm)[36]         = reinterpret_cast<float(*)[36]>(sm + LS_Z_OFF);

    const int tid = threadIdx.x;
    const int lane = tid & 31, w = tid >> 5;
    const int grp = lane >> 2, t4 = lane & 3;
    const int mf = w & 3, np = w >> 2;
    const int hb8 = blockIdx.x * 8;
    const int arow = tid >> 2, acseg = (tid & 3) * 32;   // staging map
    const unsigned mygrp = (unsigned)(blockIdx.x >> 4);

    // ---- load this block's Wh slice (32 n-rows x 1024 k) once ----
    const size_t wsrc = (size_t)blockIdx.x * 32768;
    for (int i = tid; i < 4096; i += 256) {
        int sn = i >> 7, kc8 = i & 127;
        *reinterpret_cast<float4*>(&Wsp[sn][kc8 * 8]) =
            *reinterpret_cast<const float4*>(&g_Whpk[wsrc + (size_t)sn * 1024 + kc8 * 8]);
    }
    __syncthreads();

    float c_reg[2] = {0.f, 0.f};

#pragma unroll 1
    for (int t = 0; t < T_STEPS; t++) {
        const __half* __restrict__ ah_in = g_ah[t & 1];
        __half* __restrict__ ah_out = g_ah[(t + 1) & 1];
        const float* __restrict__ xpre_t = g_Xpre + (size_t)t * (B_SZ * NG);
        float* __restrict__ out_t = out + (size_t)t * (B_SZ * H_SZ);
        const unsigned tgt = 16u * (unsigned)t;

        // prefetch this step's xpre gate-vectors
        float4 xp[2];
#pragma unroll
        for (int i = 0; i < 2; i++) {
            int p = tid + i * 256;
            int b = p >> 3, jl = p & 7;
            xp[i] = *reinterpret_cast<const float4*>(&xpre_t[(size_t)b * NG + (hb8 + jl) * 4]);
        }

        float acc[2][4] = {{0.f, 0.f, 0.f, 0.f}, {0.f, 0.f, 0.f, 0.f}};

        // chunk 0: wait + load into buf 0
        if (t) spin_ge(&g_cnt[0], tgt);
        {
            const __half* src = &ah_in[arow * 1024 + acseg];
            float4 s0 = *reinterpret_cast<const float4*>(src);
            float4 s1 = *reinterpret_cast<const float4*>(src + 8);
            float4 s2 = *reinterpret_cast<const float4*>(src + 16);
            float4 s3 = *reinterpret_cast<const float4*>(src + 24);
            __half* dst = &Ah[0][arow][acseg];
            *reinterpret_cast<float4*>(dst)      = s0;
            *reinterpret_cast<float4*>(dst + 8)  = s1;
            *reinterpret_cast<float4*>(dst + 16) = s2;
            *reinterpret_cast<float4*>(dst + 24) = s3;
        }
        __syncthreads();

#pragma unroll 1
        for (int c = 0; c < NCH; c++) {
            const int cur = c & 1;
            float4 r0v, r1v, r2v, r3v;
            if (c < NCH - 1) {
                if (t) spin_ge(&g_cnt[c + 1], tgt);
                const __half* src = &ah_in[arow * 1024 + (c + 1) * CH + acseg];
                r0v = *reinterpret_cast<const float4*>(src);
                r1v = *reinterpret_cast<const float4*>(src + 8);
                r2v = *reinterpret_cast<const float4*>(src + 16);
                r3v = *reinterpret_cast<const float4*>(src + 24);
            }
#pragma unroll
            for (int kk = 0; kk < CH; kk += 16) {
                const int r0 = mf * 16 + grp;
                const int cs = kk + 2 * t4;
                const int c0 = c * CH + cs;
                unsigned a[4], bh[2][2];
                a[0] = U32(Ah[cur][r0][cs]);     a[1] = U32(Ah[cur][r0 + 8][cs]);
                a[2] = U32(Ah[cur][r0][cs + 8]); a[3] = U32(Ah[cur][r0 + 8][cs + 8]);
#pragma unroll
                for (int q = 0; q < 2; q++) {
                    int n0 = (np * 2 + q) * 8 + grp;
                    bh[q][0] = U32(Wsp[n0][c0]); bh[q][1] = U32(Wsp[n0][c0 + 8]);
                }
                mma16816(acc[0], a, bh[0]); mma16816(acc[1], a, bh[1]);
            }
            if (c < NCH - 1) {
                __half* dst = &Ah[cur ^ 1][arow][acseg];
                *reinterpret_cast<float4*>(dst)      = r0v;
                *reinterpret_cast<float4*>(dst + 8)  = r1v;
                *reinterpret_cast<float4*>(dst + 16) = r2v;
                *reinterpret_cast<float4*>(dst + 24) = r3v;
            }
            __syncthreads();
        }

        // z exchange
#pragma unroll
        for (int q = 0; q < 2; q++) {
            int n0 = (np * 2 + q) * 8 + 2 * t4;
            int r0 = mf * 16 + grp;
            zsm[r0][n0]         = acc[q][0];
            zsm[r0][n0 + 1]     = acc[q][1];
            zsm[r0 + 8][n0]     = acc[q][2];
            zsm[r0 + 8][n0 + 1] = acc[q][3];
        }
        __syncthreads();

        // gate math + state update; publish h first, then arrive, then out
        float hn_r[2], cn_r[2];
        int idx_r[2];
#pragma unroll
        for (int i = 0; i < 2; i++) {
            int p = tid + i * 256;
            int b = p >> 3, jl = p & 7;
            int hb = hb8 + jl;
            float zf = zsm[b][jl * 4 + 0] + xp[i].x;
            float zi = zsm[b][jl * 4 + 1] + xp[i].y;
            float zg = zsm[b][jl * 4 + 2] + xp[i].z;
            float zo = zsm[b][jl * 4 + 3] + xp[i].w;
            float f  = 1.f / (1.f + expf(-zf));
            float ig = 1.f / (1.f + expf(-zi));
            float gg = tanhf(zg);
            float oo = 1.f / (1.f + expf(-zo));
            int idx = (b << 10) + hb;
            float cn = f * c_reg[i] + ig * gg;
            c_reg[i] = cn;
            float hn = oo * tanhf(cn);
            ah_out[idx] = __float2half_rn(hn);
            hn_r[i] = hn; cn_r[i] = cn; idx_r[i] = idx;
        }
        __threadfence();
        __syncthreads();
        if (tid == 0) atomicAdd(&g_cnt[mygrp], 1u);

#pragma unroll
        for (int i = 0; i < 2; i++) out_t[idx_r[i]] = hn_r[i];
        if (t == T_STEPS - 1 && out_tail) {
#pragma unroll
            for (int i = 0; i < 2; i++) {
                out_tail[idx_r[i]] = hn_r[i];
                out_tail[B_SZ * H_SZ + idx_r[i]] = cn_r[i];
            }
        }
    }
}

extern "C" void kernel_launch(void* const* d_in, const int* in_sizes, int n_in,
                              void* d_out, int out_size) {
    const float* inputs = (const float*)d_in[0];
    const float* Wf = (const float*)d_in[1];
    const float* bf = (const float*)d_in[2];
    const float* Wi = (const float*)d_in[3];
    const float* bi = (const float*)d_in[4];
    const float* Wg = (const float*)d_in[5];
    const float* bg = (const float*)d_in[6];
    const float* Wo = (const float*)d_in[7];
    const float* bo = (const float*)d_in[8];
    float* out = (float*)d_out;

    cudaFuncSetAttribute(gemm_xpre, cudaFuncAttributeMaxDynamicSharedMemorySize, GX_SMEM);
    cudaFuncSetAttribute(lstm_persist, cudaFuncAttributeMaxDynamicSharedMemorySize, LS_SMEM);

    pack_weights<<<(1024 * 1024 + 255) / 256, 256>>>(Wf, bf, Wi, bi, Wg, bg, Wo, bo);
    convert_x<<<(T_STEPS * B_SZ * 1024 + 255) / 256, 256>>>(inputs);
    zero_state<<<(B_SZ * H_SZ + 255) / 256, 256>>>();

    dim3 g1(NG / 128, (T_STEPS * B_SZ) / 128);
    gemm_xpre<<<g1, 256, GX_SMEM>>>();

    const int tail_needed = T_STEPS * B_SZ * H_SZ + 2 * B_SZ * H_SZ;
    float* out_tail = (out_size >= tail_needed) ? out + (size_t)T_STEPS * B_SZ * H_SZ : nullptr;
    lstm_persist<<<128, 256, LS_SMEM>>>(out, out_tail);
}